// round 4
// baseline (speedup 1.0000x reference)
#include <cuda_runtime.h>

// Problem dims
#define BB 16
#define WORDS 32
#define DIM 256
#define HEADS 8
#define DH 32
#define INNER 256
#define JJ 256     // WORDS*HEADS
#define IW 32      // output capsules (WORDS)
#define EE 256     // INNER

#define U_BSTRIDE ((size_t)JJ * IW * EE)

// ---------------- scratch (device globals; no allocations) ----------------
__device__ float g_xh[BB * JJ * DH];                  // [b][j][d]
__device__ float g_u[(size_t)BB * JJ * IW * EE];      // [b][j][i][e]  (128 MiB)
__device__ float g_S[3][BB * IW * EE];                // s accumulators per iter
__device__ float g_blog[BB * JJ * IW];                // routing logits

// ---------------- f32x2 helpers ----------------
typedef unsigned long long u64;

__device__ __forceinline__ u64 pack2(float lo, float hi) {
    u64 r;
    asm("mov.b64 %0, {%1, %2};" : "=l"(r)
        : "r"(__float_as_uint(lo)), "r"(__float_as_uint(hi)));
    return r;
}
__device__ __forceinline__ void unpack2(u64 v, float& lo, float& hi) {
    unsigned a, b;
    asm("mov.b64 {%0, %1}, %2;" : "=r"(a), "=r"(b) : "l"(v));
    lo = __uint_as_float(a);
    hi = __uint_as_float(b);
}
__device__ __forceinline__ void fma2(u64& acc, u64 a, u64 b) {
    asm("fma.rn.f32x2 %0, %1, %2, %0;" : "+l"(acc) : "l"(a), "l"(b));
}
__device__ __forceinline__ void add2(u64& acc, u64 a) {
    asm("add.rn.f32x2 %0, %1, %2;" : "=l"(acc) : "l"(acc), "l"(a));
}

// ---------------- K0 a/b/c: zero one S buffer each ----------------
__global__ void k_zero(int which) {
    int t = blockIdx.x * 256 + threadIdx.x;
    ((float4*)g_S[which])[t] = make_float4(0.f, 0.f, 0.f, 0.f);
}

// ---------------- K1 (x2): inner projection  xh[b][j][d] ----------------
__global__ void __launch_bounds__(256) k_proj_in(const float* __restrict__ x,
                                                 const float* __restrict__ Wi,
                                                 const float* __restrict__ bi,
                                                 int b0) {
    int b  = blockIdx.y + b0;
    int eb = blockIdx.x;
    __shared__ float xs[32][DIM];
    __shared__ float ws[32][33];

    int tid = threadIdx.x;
    const float4* xg = (const float4*)(x + (size_t)b * 32 * DIM);
    float4* xs4 = (float4*)xs;
    for (int idx = tid; idx < 32 * DIM / 4; idx += 256) xs4[idx] = xg[idx];

    int el = tid & 31;
    int n0 = (tid >> 5) * 4;
    float acc[4] = {0.f, 0.f, 0.f, 0.f};

    for (int kt = 0; kt < 8; kt++) {
        __syncthreads();
        {
            int r = tid >> 5, c = tid & 31;
            for (int rr = r; rr < 32; rr += 8)
                ws[rr][c] = Wi[(size_t)(eb * 32 + rr) * DIM + kt * 32 + c];
        }
        __syncthreads();
#pragma unroll
        for (int k = 0; k < 32; k++) {
            float wv = ws[el][k];
#pragma unroll
            for (int r = 0; r < 4; r++)
                acc[r] = fmaf(xs[n0 + r][kt * 32 + k], wv, acc[r]);
        }
    }

    int ee = eb * 32 + el;
    float bv = bi[ee];
    int h = ee >> 5, d = ee & 31;
#pragma unroll
    for (int r = 0; r < 4; r++) {
        int n = n0 + r;
        g_xh[((size_t)b * JJ + n * HEADS + h) * DH + d] = acc[r] + bv;
    }
}

// ---------------- cp.async helpers ----------------
__device__ __forceinline__ void uhat_issue_tile(const float4* __restrict__ Wg,
                                                float4* dst, int e) {
#pragma unroll
    for (int k = 0; k < 8; k++) {
        int idx = e + k * 256;                 // coalesced: warp = 512B contiguous
        int er = idx >> 3, q = idx & 7;
        unsigned sp = (unsigned)__cvta_generic_to_shared(
            &dst[(er << 3) | (q ^ (er & 7))]); // XOR swizzle
        asm volatile("cp.async.cg.shared.global [%0], [%1], 16;"
                     :: "r"(sp), "l"(Wg + idx));
    }
    asm volatile("cp.async.commit_group;");
}

// ---------------- K2: u_hat einsum, cp.async double-buffered ----------------
// u[b,j,i,e] = sum_d W[j,i,e,d]*xh[b,j,d] + bias[j,i,e]; fused iter-0 sum.
__global__ void __launch_bounds__(256, 2) k_uhat(const float* __restrict__ W,
                                                 const float* __restrict__ bias) {
    extern __shared__ __align__(16) unsigned char dynraw[];
    float4* s_w = (float4*)dynraw;                        // [2][2048] = 64 KB
    float*  sxh = (float*)(dynraw + 65536);               // [8][32][16] = 16 KB

    int i  = blockIdx.y;   // 0..31
    int jb = blockIdx.x;   // 0..31
    int e  = threadIdx.x;  // 0..255

    for (int idx = threadIdx.x; idx < 8 * 512; idx += 256) {
        int jj  = idx >> 9;
        int rem = idx & 511;
        int b   = rem >> 5;
        int d   = rem & 31;
        sxh[jj * 512 + d * 16 + b] =
            g_xh[((size_t)b * JJ + jb * 8 + jj) * DH + d];
    }

    float bv8[8];
#pragma unroll
    for (int jj = 0; jj < 8; jj++)
        bv8[jj] = bias[((size_t)(jb * 8 + jj) * IW + i) * EE + e];

    const float4* Wbase = (const float4*)W;
    uhat_issue_tile(Wbase + ((size_t)(jb * 8) * IW + i) * 2048, s_w, e);

    u64 sacc[8];
#pragma unroll
    for (int p = 0; p < 8; p++) sacc[p] = 0ull;

    for (int jj = 0; jj < 8; jj++) {
        if (jj < 7) {
            uhat_issue_tile(Wbase + ((size_t)(jb * 8 + jj + 1) * IW + i) * 2048,
                            s_w + ((jj + 1) & 1) * 2048, e);
            asm volatile("cp.async.wait_group 1;");
        } else {
            asm volatile("cp.async.wait_group 0;");
        }
        __syncthreads();

        const float4* sw = s_w + (jj & 1) * 2048;
        float4 w4[8];
#pragma unroll
        for (int q = 0; q < 8; q++) w4[q] = sw[(e << 3) | (q ^ (e & 7))];

        u64 acc[8];
#pragma unroll
        for (int p = 0; p < 8; p++) acc[p] = 0ull;

        const float* sx = sxh + jj * 512;
#pragma unroll
        for (int q = 0; q < 8; q++) {
            float4 wq = w4[q];
#pragma unroll
            for (int c = 0; c < 4; c++) {
                float wv = (c == 0) ? wq.x : (c == 1) ? wq.y : (c == 2) ? wq.z : wq.w;
                int d = q * 4 + c;
                u64 w2 = pack2(wv, wv);
                const ulonglong2* row = (const ulonglong2*)(sx + d * 16);
#pragma unroll
                for (int m = 0; m < 4; m++) {
                    ulonglong2 xv = row[m];
                    fma2(acc[2 * m], w2, xv.x);
                    fma2(acc[2 * m + 1], w2, xv.y);
                }
            }
        }

        u64 b2 = pack2(bv8[jj], bv8[jj]);
        size_t base = (size_t)(jb * 8 + jj) * (IW * EE) + (size_t)i * EE + e;
#pragma unroll
        for (int p = 0; p < 8; p++) {
            u64 uv = acc[p];
            add2(uv, b2);
            add2(sacc[p], uv);
            float lo, hi;
            unpack2(uv, lo, hi);
            g_u[base + (size_t)(2 * p) * U_BSTRIDE]     = lo;
            g_u[base + (size_t)(2 * p + 1) * U_BSTRIDE] = hi;
        }
        __syncthreads();
    }

#pragma unroll
    for (int p = 0; p < 8; p++) {
        float lo, hi;
        unpack2(sacc[p], lo, hi);
        atomicAdd(&g_S[0][(2 * p) * (IW * EE) + i * EE + e], lo);
        atomicAdd(&g_S[0][(2 * p + 1) * (IW * EE) + i * EE + e], hi);
    }
}

// ---------------- routing pass (fused squash prologue, 1 sync/jj) ----------
// v = squash(S[sin]*scale); a = dot(u, v); PASS1: blog=a, c=softmax(a)
//                                          PASS2: c=softmax(blog+a)
// S[sout] += sum_j c*u
template <int PASS>
__global__ void __launch_bounds__(256, 2) k_route(int sin, int sout, float scale) {
    int jb = blockIdx.x;   // 0..15 (16 j per block)
    int b  = blockIdx.y;   // 0..15
    int tid = threadIdx.x, w = tid >> 5, l = tid & 31;

    __shared__ float vs[IW][EE];   // 32 KB
    __shared__ float a_s[2][IW];

    // load S*scale
    const float4* sg4 = (const float4*)(g_S[sin] + (size_t)b * IW * EE);
    float4* vs4 = (float4*)vs;
    for (int idx = tid; idx < IW * EE / 4; idx += 256) {
        float4 v = sg4[idx];
        v.x *= scale; v.y *= scale; v.z *= scale; v.w *= scale;
        vs4[idx] = v;
    }
    __syncthreads();
    // in-place squash (bank-staggered)
    {
        int i = tid >> 3, seg = tid & 7;
        float ps = 0.f;
#pragma unroll
        for (int k = 0; k < 32; k++) {
            int e = seg * 32 + ((k + tid) & 31);
            float x = vs[i][e];
            ps = fmaf(x, x, ps);
        }
        ps += __shfl_xor_sync(0xffffffffu, ps, 1);
        ps += __shfl_xor_sync(0xffffffffu, ps, 2);
        ps += __shfl_xor_sync(0xffffffffu, ps, 4);
        float f = sqrtf(ps) / (1.0f + ps);
#pragma unroll
        for (int k = 0; k < 32; k++) {
            int e = seg * 32 + ((k + tid) & 31);
            vs[i][e] *= f;
        }
    }
    __syncthreads();

    float4 sacc[4][2];
#pragma unroll
    for (int s = 0; s < 4; s++) {
        sacc[s][0] = make_float4(0.f, 0.f, 0.f, 0.f);
        sacc[s][1] = make_float4(0.f, 0.f, 0.f, 0.f);
    }

    const float* ubase = g_u + (size_t)b * U_BSTRIDE;

    float4 cur[4][2];
    {
        int j0 = jb * 16;
#pragma unroll
        for (int s = 0; s < 4; s++) {
            int i = w + s * 8;
            const float4* up = (const float4*)(ubase + ((size_t)j0 * IW + i) * EE + l * 8);
            cur[s][0] = up[0];
            cur[s][1] = up[1];
        }
    }

    for (int jj = 0; jj < 16; jj++) {
        int j = jb * 16 + jj;

        float4 nxt[4][2];
        if (jj < 15) {
            int jn = j + 1;
#pragma unroll
            for (int s = 0; s < 4; s++) {
                int i = w + s * 8;
                const float4* up = (const float4*)(ubase + ((size_t)jn * IW + i) * EE + l * 8);
                nxt[s][0] = up[0];
                nxt[s][1] = up[1];
            }
        }

#pragma unroll
        for (int s = 0; s < 4; s++) {
            int i = w + s * 8;
            const float4* vp = (const float4*)(&vs[i][l * 8]);
            float4 va = vp[0];
            float4 vc = vp[1];
            float4 a = cur[s][0], c4 = cur[s][1];
            float dot = a.x * va.x + a.y * va.y + a.z * va.z + a.w * va.w +
                        c4.x * vc.x + c4.y * vc.y + c4.z * vc.z + c4.w * vc.w;
#pragma unroll
            for (int o = 16; o; o >>= 1) dot += __shfl_xor_sync(0xffffffffu, dot, o);
            if (l == 0) a_s[jj & 1][i] = dot;
        }
        __syncthreads();   // single barrier per jj

        // redundant softmax in every warp (lane l <-> capsule i=l)
        float z = a_s[jj & 1][l];
        if (PASS == 2) {
            z += g_blog[((size_t)b * JJ + j) * IW + l];
        } else {
            if (w == 0) g_blog[((size_t)b * JJ + j) * IW + l] = z;
        }
        float mx = z;
#pragma unroll
        for (int o = 16; o; o >>= 1) mx = fmaxf(mx, __shfl_xor_sync(0xffffffffu, mx, o));
        float p = __expf(z - mx);
        float sm = p;
#pragma unroll
        for (int o = 16; o; o >>= 1) sm += __shfl_xor_sync(0xffffffffu, sm, o);
        float c_all = p / sm;

#pragma unroll
        for (int s = 0; s < 4; s++) {
            float c = __shfl_sync(0xffffffffu, c_all, w + s * 8);
            sacc[s][0].x = fmaf(c, cur[s][0].x, sacc[s][0].x);
            sacc[s][0].y = fmaf(c, cur[s][0].y, sacc[s][0].y);
            sacc[s][0].z = fmaf(c, cur[s][0].z, sacc[s][0].z);
            sacc[s][0].w = fmaf(c, cur[s][0].w, sacc[s][0].w);
            sacc[s][1].x = fmaf(c, cur[s][1].x, sacc[s][1].x);
            sacc[s][1].y = fmaf(c, cur[s][1].y, sacc[s][1].y);
            sacc[s][1].z = fmaf(c, cur[s][1].z, sacc[s][1].z);
            sacc[s][1].w = fmaf(c, cur[s][1].w, sacc[s][1].w);
        }
#pragma unroll
        for (int s = 0; s < 4; s++) {
            cur[s][0] = nxt[s][0];
            cur[s][1] = nxt[s][1];
        }
    }

    float* So = g_S[sout] + (size_t)b * IW * EE;
#pragma unroll
    for (int s = 0; s < 4; s++) {
        int i = w + s * 8;
        float* sp = &So[i * EE + l * 8];
        atomicAdd(sp + 0, sacc[s][0].x);
        atomicAdd(sp + 1, sacc[s][0].y);
        atomicAdd(sp + 2, sacc[s][0].z);
        atomicAdd(sp + 3, sacc[s][0].w);
        atomicAdd(sp + 4, sacc[s][1].x);
        atomicAdd(sp + 5, sacc[s][1].y);
        atomicAdd(sp + 6, sacc[s][1].z);
        atomicAdd(sp + 7, sacc[s][1].w);
    }
}

// ---------------- K8: output projection (fused final squash) ----------------
__global__ void __launch_bounds__(256) k_proj_out(const float* __restrict__ Wo,
                                                  const float* __restrict__ bo,
                                                  float* __restrict__ out) {
    int b  = blockIdx.y;
    int db = blockIdx.x;
    __shared__ float vvs[32][EE];
    __shared__ float wos[32][33];

    int tid = threadIdx.x;
    const float4* sg4 = (const float4*)(g_S[2] + (size_t)b * IW * EE);
    float4* vv4 = (float4*)vvs;
    for (int idx = tid; idx < IW * EE / 4; idx += 256) vv4[idx] = sg4[idx];
    __syncthreads();
    // in-place squash
    {
        int i = tid >> 3, seg = tid & 7;
        float ps = 0.f;
#pragma unroll
        for (int k = 0; k < 32; k++) {
            int e = seg * 32 + ((k + tid) & 31);
            float x = vvs[i][e];
            ps = fmaf(x, x, ps);
        }
        ps += __shfl_xor_sync(0xffffffffu, ps, 1);
        ps += __shfl_xor_sync(0xffffffffu, ps, 2);
        ps += __shfl_xor_sync(0xffffffffu, ps, 4);
        float f = sqrtf(ps) / (1.0f + ps);
#pragma unroll
        for (int k = 0; k < 32; k++) {
            int e = seg * 32 + ((k + tid) & 31);
            vvs[i][e] *= f;
        }
    }

    int dl = tid & 31;
    int n0 = (tid >> 5) * 4;
    float acc[4] = {0.f, 0.f, 0.f, 0.f};

    for (int et = 0; et < 8; et++) {
        __syncthreads();
        {
            int r = tid >> 5, c = tid & 31;
            for (int rr = r; rr < 32; rr += 8)
                wos[rr][c] = Wo[(size_t)(db * 32 + rr) * EE + et * 32 + c];
        }
        __syncthreads();
#pragma unroll
        for (int k = 0; k < 32; k++) {
            float wv = wos[dl][k];
#pragma unroll
            for (int r = 0; r < 4; r++)
                acc[r] = fmaf(vvs[n0 + r][et * 32 + k], wv, acc[r]);
        }
    }

    int dm = db * 32 + dl;
    float bv = bo[dm];
#pragma unroll
    for (int r = 0; r < 4; r++)
        out[((size_t)b * WORDS + n0 + r) * DIM + dm] = acc[r] + bv;
}

// ---------------- launch ----------------
extern "C" void kernel_launch(void* const* d_in, const int* in_sizes, int n_in,
                              void* d_out, int out_size) {
    const float* x    = (const float*)d_in[0];
    const float* W    = (const float*)d_in[1];
    const float* bias = (const float*)d_in[2];
    const float* Wi   = (const float*)d_in[3];
    const float* bi   = (const float*)d_in[4];
    const float* Wo   = (const float*)d_in[5];
    const float* bo   = (const float*)d_in[6];
    float* out = (float*)d_out;

    cudaFuncSetAttribute(k_uhat, cudaFuncAttributeMaxDynamicSharedMemorySize,
                         81920);

    int zgrid = (BB * IW * EE) / (256 * 4);
    k_zero<<<zgrid, 256>>>(0);                          // launch 1
    k_zero<<<zgrid, 256>>>(1);                          // launch 2
    k_zero<<<zgrid, 256>>>(2);                          // launch 3
    k_proj_in<<<dim3(8, 8), 256>>>(x, Wi, bi, 0);       // launch 4
    k_proj_in<<<dim3(8, 8), 256>>>(x, Wi, bi, 8);       // launch 5
    k_uhat<<<dim3(32, 32), 256, 81920>>>(W, bias);      // launch 6 (ncu target)
    k_route<1><<<dim3(16, BB), 256>>>(0, 1, 1.0f / 32.0f);
    k_route<2><<<dim3(16, BB), 256>>>(1, 2, 1.0f);
    k_proj_out<<<dim3(8, BB), 256>>>(Wo, bo, out);
}

// round 5
// speedup vs baseline: 1.1533x; 1.1533x over previous
#include <cuda_runtime.h>

// Problem dims
#define BB 16
#define WORDS 32
#define DIM 256
#define HEADS 8
#define DH 32
#define INNER 256
#define JJ 256     // WORDS*HEADS
#define IW 32      // output capsules (WORDS)
#define EE 256     // INNER

#define U_BSTRIDE ((size_t)JJ * IW * EE)

// ---------------- scratch (device globals; no allocations) ----------------
__device__ float g_xh[BB * JJ * DH];                  // [b][j][d]
__device__ float g_u[(size_t)BB * JJ * IW * EE];      // [b][j][i][e]  (128 MiB)
__device__ float g_S[3][BB * IW * EE];                // s accumulators per iter
__device__ float g_blog[BB * JJ * IW];                // routing logits

// ---------------- f32x2 helpers ----------------
typedef unsigned long long u64;

__device__ __forceinline__ u64 pack2(float lo, float hi) {
    u64 r;
    asm("mov.b64 %0, {%1, %2};" : "=l"(r)
        : "r"(__float_as_uint(lo)), "r"(__float_as_uint(hi)));
    return r;
}
__device__ __forceinline__ void unpack2(u64 v, float& lo, float& hi) {
    unsigned a, b;
    asm("mov.b64 {%0, %1}, %2;" : "=r"(a), "=r"(b) : "l"(v));
    lo = __uint_as_float(a);
    hi = __uint_as_float(b);
}
__device__ __forceinline__ void fma2(u64& acc, u64 a, u64 b) {
    asm("fma.rn.f32x2 %0, %1, %2, %0;" : "+l"(acc) : "l"(a), "l"(b));
}
__device__ __forceinline__ void add2(u64& acc, u64 a) {
    asm("add.rn.f32x2 %0, %1, %2;" : "=l"(acc) : "l"(acc), "l"(a));
}

// ---------------- K1: inner projection (single launch, fuses S0 zeroing) ----
// xi[b,n,ee] = sum_k x[b,n,k]*Wi[ee,k] + bi[ee]
__global__ void __launch_bounds__(256) k_proj_in(const float* __restrict__ x,
                                                 const float* __restrict__ Wi,
                                                 const float* __restrict__ bi) {
    extern __shared__ float dynpi[];
    float* xs = dynpi;              // [32][256]  32 KB
    float* ws = dynpi + 8192;       // [32][257]  ~32.9 KB (padded stride)

    int eb = blockIdx.x;   // 0..7
    int b  = blockIdx.y;   // 0..15
    int tid = threadIdx.x;

    // zero my slice of S0 (2 MB / 128 blocks = 1024 float4)
    {
        float4* z = (float4*)(&g_S[0][0]) + (size_t)(eb * 16 + b) * 1024;
#pragma unroll
        for (int r = 0; r < 4; r++)
            z[tid + r * 256] = make_float4(0.f, 0.f, 0.f, 0.f);
    }

    // stage x[b] and Wi slab once
    {
        const float4* xg = (const float4*)(x + (size_t)b * 32 * DIM);
        float4* xs4 = (float4*)xs;
#pragma unroll
        for (int r = 0; r < 8; r++) xs4[tid + r * 256] = xg[tid + r * 256];

        int rr = tid >> 5, c = tid & 31;
        for (int row = rr; row < 32; row += 8) {
            const float* wr = Wi + (size_t)(eb * 32 + row) * DIM;
#pragma unroll
            for (int kk = 0; kk < 8; kk++)
                ws[row * 257 + kk * 32 + c] = wr[kk * 32 + c];
        }
    }
    __syncthreads();

    int el = tid & 31;
    int n0 = (tid >> 5) * 4;
    float acc[4] = {0.f, 0.f, 0.f, 0.f};

#pragma unroll 4
    for (int k = 0; k < 256; k++) {
        float wv = ws[el * 257 + k];
#pragma unroll
        for (int r = 0; r < 4; r++)
            acc[r] = fmaf(xs[(n0 + r) * 256 + k], wv, acc[r]);
    }

    int ee = eb * 32 + el;
    float bv = bi[ee];
    int h = ee >> 5, d = ee & 31;
#pragma unroll
    for (int r = 0; r < 4; r++) {
        int n = n0 + r;
        g_xh[((size_t)b * JJ + n * HEADS + h) * DH + d] = acc[r] + bv;
    }
}

// ---------------- cp.async helpers ----------------
__device__ __forceinline__ void uhat_issue_tile(const float4* __restrict__ Wg,
                                                float4* dst, int e) {
#pragma unroll
    for (int k = 0; k < 8; k++) {
        int idx = e + k * 256;
        int er = idx >> 3, q = idx & 7;
        unsigned sp = (unsigned)__cvta_generic_to_shared(
            &dst[(er << 3) | (q ^ (er & 7))]);
        asm volatile("cp.async.cg.shared.global [%0], [%1], 16;"
                     :: "r"(sp), "l"(Wg + idx));
    }
    asm volatile("cp.async.commit_group;");
}

// ---------------- K2: u_hat einsum (cp.async dbl-buffer, fuses S1 zero) ----
__global__ void __launch_bounds__(256, 2) k_uhat(const float* __restrict__ W,
                                                 const float* __restrict__ bias) {
    extern __shared__ __align__(16) unsigned char dynraw[];
    float4* s_w = (float4*)dynraw;                        // [2][2048] = 64 KB
    float*  sxh = (float*)(dynraw + 65536);               // [8][32][16] = 16 KB

    int i  = blockIdx.y;   // 0..31
    int jb = blockIdx.x;   // 0..31
    int e  = threadIdx.x;  // 0..255

    // zero my slice of S1 (2 MB / 1024 blocks = 128 float4)
    if (e < 128)
        ((float4*)(&g_S[1][0]))[(size_t)(jb * 32 + i) * 128 + e] =
            make_float4(0.f, 0.f, 0.f, 0.f);

    for (int idx = threadIdx.x; idx < 8 * 512; idx += 256) {
        int jj  = idx >> 9;
        int rem = idx & 511;
        int b   = rem >> 5;
        int d   = rem & 31;
        sxh[jj * 512 + d * 16 + b] =
            g_xh[((size_t)b * JJ + jb * 8 + jj) * DH + d];
    }

    float bv8[8];
#pragma unroll
    for (int jj = 0; jj < 8; jj++)
        bv8[jj] = bias[((size_t)(jb * 8 + jj) * IW + i) * EE + e];

    const float4* Wbase = (const float4*)W;
    uhat_issue_tile(Wbase + ((size_t)(jb * 8) * IW + i) * 2048, s_w, e);

    u64 sacc[8];
#pragma unroll
    for (int p = 0; p < 8; p++) sacc[p] = 0ull;

    for (int jj = 0; jj < 8; jj++) {
        if (jj < 7) {
            uhat_issue_tile(Wbase + ((size_t)(jb * 8 + jj + 1) * IW + i) * 2048,
                            s_w + ((jj + 1) & 1) * 2048, e);
            asm volatile("cp.async.wait_group 1;");
        } else {
            asm volatile("cp.async.wait_group 0;");
        }
        __syncthreads();

        const float4* sw = s_w + (jj & 1) * 2048;
        float4 w4[8];
#pragma unroll
        for (int q = 0; q < 8; q++) w4[q] = sw[(e << 3) | (q ^ (e & 7))];

        u64 acc[8];
#pragma unroll
        for (int p = 0; p < 8; p++) acc[p] = 0ull;

        const float* sx = sxh + jj * 512;
#pragma unroll
        for (int q = 0; q < 8; q++) {
            float4 wq = w4[q];
#pragma unroll
            for (int c = 0; c < 4; c++) {
                float wv = (c == 0) ? wq.x : (c == 1) ? wq.y : (c == 2) ? wq.z : wq.w;
                int d = q * 4 + c;
                u64 w2 = pack2(wv, wv);
                const ulonglong2* row = (const ulonglong2*)(sx + d * 16);
#pragma unroll
                for (int m = 0; m < 4; m++) {
                    ulonglong2 xv = row[m];
                    fma2(acc[2 * m], w2, xv.x);
                    fma2(acc[2 * m + 1], w2, xv.y);
                }
            }
        }

        u64 b2 = pack2(bv8[jj], bv8[jj]);
        size_t base = (size_t)(jb * 8 + jj) * (IW * EE) + (size_t)i * EE + e;
#pragma unroll
        for (int p = 0; p < 8; p++) {
            u64 uv = acc[p];
            add2(uv, b2);
            add2(sacc[p], uv);
            float lo, hi;
            unpack2(uv, lo, hi);
            g_u[base + (size_t)(2 * p) * U_BSTRIDE]     = lo;
            g_u[base + (size_t)(2 * p + 1) * U_BSTRIDE] = hi;
        }
        __syncthreads();
    }

#pragma unroll
    for (int p = 0; p < 8; p++) {
        float lo, hi;
        unpack2(sacc[p], lo, hi);
        atomicAdd(&g_S[0][(2 * p) * (IW * EE) + i * EE + e], lo);
        atomicAdd(&g_S[0][(2 * p + 1) * (IW * EE) + i * EE + e], hi);
    }
}

// ---------------- routing pass (cp.async staged u, fused squash) -----------
// v = squash(S[sin]*scale); a = dot(u,v); PASS1: blog=a, c=softmax(a), zero S2
//                                          PASS2: c=softmax(blog+a)
template <int PASS>
__global__ void __launch_bounds__(256) k_route(int sin, int sout, float scale) {
    extern __shared__ __align__(16) float dynr[];
    float* vs = dynr;            // [32][256] 32 KB
    float* su = dynr + 8192;     // [2][8192] 64 KB
    __shared__ float a_s[2][IW];

    int jb = blockIdx.x;   // 0..15 (16 j per block)
    int b  = blockIdx.y;   // 0..15
    int tid = threadIdx.x, w = tid >> 5, l = tid & 31;

    const float* ubase = g_u + (size_t)b * U_BSTRIDE + (size_t)(jb * 16) * (IW * EE);

    // issue stage for local jj
    auto issue = [&](int jj) {
        const float4* src = (const float4*)(ubase + (size_t)jj * (IW * EE));
        float4* dst = (float4*)(su + (jj & 1) * 8192);
#pragma unroll
        for (int k = 0; k < 8; k++) {
            unsigned sp = (unsigned)__cvta_generic_to_shared(dst + tid + k * 256);
            asm volatile("cp.async.cg.shared.global [%0], [%1], 16;"
                         :: "r"(sp), "l"(src + tid + k * 256));
        }
        asm volatile("cp.async.commit_group;");
    };

    issue(0);
    issue(1);

    if (PASS == 1) {   // zero my slice of S2 (2 MB / 256 blocks = 512 float4)
        float4* z = (float4*)(&g_S[2][0]) + (size_t)(b * 16 + jb) * 512;
        z[tid] = make_float4(0.f, 0.f, 0.f, 0.f);
        z[tid + 256] = make_float4(0.f, 0.f, 0.f, 0.f);
    }

    // load S[sin]*scale into vs, then in-place squash
    {
        const float4* sg4 = (const float4*)(g_S[sin] + (size_t)b * IW * EE);
        float4* vs4 = (float4*)vs;
#pragma unroll
        for (int r = 0; r < 8; r++) {
            float4 v = sg4[tid + r * 256];
            v.x *= scale; v.y *= scale; v.z *= scale; v.w *= scale;
            vs4[tid + r * 256] = v;
        }
    }
    __syncthreads();
    {
        int i = tid >> 3, seg = tid & 7;
        float ps = 0.f;
#pragma unroll
        for (int k = 0; k < 32; k++) {
            int e = seg * 32 + ((k + tid) & 31);
            float xv = vs[i * 256 + e];
            ps = fmaf(xv, xv, ps);
        }
        ps += __shfl_xor_sync(0xffffffffu, ps, 1);
        ps += __shfl_xor_sync(0xffffffffu, ps, 2);
        ps += __shfl_xor_sync(0xffffffffu, ps, 4);
        float f = sqrtf(ps) / (1.0f + ps);
#pragma unroll
        for (int k = 0; k < 32; k++) {
            int e = seg * 32 + ((k + tid) & 31);
            vs[i * 256 + e] *= f;
        }
    }

    float4 sacc[4][2];
#pragma unroll
    for (int s = 0; s < 4; s++) {
        sacc[s][0] = make_float4(0.f, 0.f, 0.f, 0.f);
        sacc[s][1] = make_float4(0.f, 0.f, 0.f, 0.f);
    }

    for (int jj = 0; jj < 16; jj++) {
        int j = jb * 16 + jj;

        if (jj < 15) asm volatile("cp.async.wait_group 1;");
        else         asm volatile("cp.async.wait_group 0;");
        __syncthreads();   // stage (jj&1) visible to all; vs squash covered on jj==0

        // snapshot u into registers, compute agreement dots
        const float* st = su + (jj & 1) * 8192;
        float4 ur[4][2];
#pragma unroll
        for (int s = 0; s < 4; s++) {
            int i = w + s * 8;
            const float4* up = (const float4*)(st + i * 256 + l * 8);
            ur[s][0] = up[0];
            ur[s][1] = up[1];
            const float4* vp = (const float4*)(vs + i * 256 + l * 8);
            float4 va = vp[0], vc = vp[1];
            float dot = ur[s][0].x * va.x + ur[s][0].y * va.y +
                        ur[s][0].z * va.z + ur[s][0].w * va.w +
                        ur[s][1].x * vc.x + ur[s][1].y * vc.y +
                        ur[s][1].z * vc.z + ur[s][1].w * vc.w;
#pragma unroll
            for (int o = 16; o; o >>= 1) dot += __shfl_xor_sync(0xffffffffu, dot, o);
            if (l == 0) a_s[jj & 1][i] = dot;
        }
        __syncthreads();   // a_s ready AND stage fully consumed (ur in regs)

        if (jj < 14) issue(jj + 2);   // safe: stage (jj&1) no longer read

        // redundant softmax in every warp (lane l <-> capsule i=l)
        float z = a_s[jj & 1][l];
        if (PASS == 2) {
            z += g_blog[((size_t)b * JJ + j) * IW + l];
        } else {
            if (w == 0) g_blog[((size_t)b * JJ + j) * IW + l] = z;
        }
        float mx = z;
#pragma unroll
        for (int o = 16; o; o >>= 1) mx = fmaxf(mx, __shfl_xor_sync(0xffffffffu, mx, o));
        float p = __expf(z - mx);
        float sm = p;
#pragma unroll
        for (int o = 16; o; o >>= 1) sm += __shfl_xor_sync(0xffffffffu, sm, o);
        float c_all = p / sm;

#pragma unroll
        for (int s = 0; s < 4; s++) {
            float c = __shfl_sync(0xffffffffu, c_all, w + s * 8);
            sacc[s][0].x = fmaf(c, ur[s][0].x, sacc[s][0].x);
            sacc[s][0].y = fmaf(c, ur[s][0].y, sacc[s][0].y);
            sacc[s][0].z = fmaf(c, ur[s][0].z, sacc[s][0].z);
            sacc[s][0].w = fmaf(c, ur[s][0].w, sacc[s][0].w);
            sacc[s][1].x = fmaf(c, ur[s][1].x, sacc[s][1].x);
            sacc[s][1].y = fmaf(c, ur[s][1].y, sacc[s][1].y);
            sacc[s][1].z = fmaf(c, ur[s][1].z, sacc[s][1].z);
            sacc[s][1].w = fmaf(c, ur[s][1].w, sacc[s][1].w);
        }
    }

    float* So = g_S[sout] + (size_t)b * IW * EE;
#pragma unroll
    for (int s = 0; s < 4; s++) {
        int i = w + s * 8;
        float* sp = &So[i * EE + l * 8];
        atomicAdd(sp + 0, sacc[s][0].x);
        atomicAdd(sp + 1, sacc[s][0].y);
        atomicAdd(sp + 2, sacc[s][0].z);
        atomicAdd(sp + 3, sacc[s][0].w);
        atomicAdd(sp + 4, sacc[s][1].x);
        atomicAdd(sp + 5, sacc[s][1].y);
        atomicAdd(sp + 6, sacc[s][1].z);
        atomicAdd(sp + 7, sacc[s][1].w);
    }
}

// ---------------- K8: output projection (fused final squash) ----------------
__global__ void __launch_bounds__(256) k_proj_out(const float* __restrict__ Wo,
                                                  const float* __restrict__ bo,
                                                  float* __restrict__ out) {
    int b  = blockIdx.y;
    int db = blockIdx.x;
    __shared__ float vvs[32][EE];
    __shared__ float wos[32][33];

    int tid = threadIdx.x;
    const float4* sg4 = (const float4*)(g_S[2] + (size_t)b * IW * EE);
    float4* vv4 = (float4*)vvs;
    for (int idx = tid; idx < IW * EE / 4; idx += 256) vv4[idx] = sg4[idx];
    __syncthreads();
    {
        int i = tid >> 3, seg = tid & 7;
        float ps = 0.f;
#pragma unroll
        for (int k = 0; k < 32; k++) {
            int e = seg * 32 + ((k + tid) & 31);
            float xv = vvs[i][e];
            ps = fmaf(xv, xv, ps);
        }
        ps += __shfl_xor_sync(0xffffffffu, ps, 1);
        ps += __shfl_xor_sync(0xffffffffu, ps, 2);
        ps += __shfl_xor_sync(0xffffffffu, ps, 4);
        float f = sqrtf(ps) / (1.0f + ps);
#pragma unroll
        for (int k = 0; k < 32; k++) {
            int e = seg * 32 + ((k + tid) & 31);
            vvs[i][e] *= f;
        }
    }

    int dl = tid & 31;
    int n0 = (tid >> 5) * 4;
    float acc[4] = {0.f, 0.f, 0.f, 0.f};

    for (int et = 0; et < 8; et++) {
        __syncthreads();
        {
            int r = tid >> 5, c = tid & 31;
            for (int rr = r; rr < 32; rr += 8)
                wos[rr][c] = Wo[(size_t)(db * 32 + rr) * EE + et * 32 + c];
        }
        __syncthreads();
#pragma unroll
        for (int k = 0; k < 32; k++) {
            float wv = wos[dl][k];
#pragma unroll
            for (int r = 0; r < 4; r++)
                acc[r] = fmaf(vvs[n0 + r][et * 32 + k], wv, acc[r]);
        }
    }

    int dm = db * 32 + dl;
    float bv = bo[dm];
#pragma unroll
    for (int r = 0; r < 4; r++)
        out[((size_t)b * WORDS + n0 + r) * DIM + dm] = acc[r] + bv;
}

// ---------------- launch ----------------
extern "C" void kernel_launch(void* const* d_in, const int* in_sizes, int n_in,
                              void* d_out, int out_size) {
    const float* x    = (const float*)d_in[0];
    const float* W    = (const float*)d_in[1];
    const float* bias = (const float*)d_in[2];
    const float* Wi   = (const float*)d_in[3];
    const float* bi   = (const float*)d_in[4];
    const float* Wo   = (const float*)d_in[5];
    const float* bo   = (const float*)d_in[6];
    float* out = (float*)d_out;

    static bool attr_done = false;
    if (!attr_done) {
        cudaFuncSetAttribute(k_proj_in,
                             cudaFuncAttributeMaxDynamicSharedMemorySize, 66688);
        cudaFuncSetAttribute(k_uhat,
                             cudaFuncAttributeMaxDynamicSharedMemorySize, 81920);
        cudaFuncSetAttribute(k_route<1>,
                             cudaFuncAttributeMaxDynamicSharedMemorySize, 98304);
        cudaFuncSetAttribute(k_route<2>,
                             cudaFuncAttributeMaxDynamicSharedMemorySize, 98304);
        attr_done = true;
    }

    k_proj_in<<<dim3(8, BB), 256, 66688>>>(x, Wi, bi);            // 1
    k_uhat<<<dim3(32, 32), 256, 81920>>>(W, bias);                // 2
    k_route<1><<<dim3(16, BB), 256, 98304>>>(0, 1, 1.0f / 32.0f); // 3
    k_route<2><<<dim3(16, BB), 256, 98304>>>(1, 2, 1.0f);         // 4 (ncu)
    k_proj_out<<<dim3(8, BB), 256>>>(Wo, bo, out);                // 5
}